// round 5
// baseline (speedup 1.0000x reference)
#include <cuda_runtime.h>
#include <cuda_bf16.h>
#include <cstdint>
#include <math.h>

// Problem constants
#define E_  8
#define CC  2048   // tokens per expert (G*C)
#define HH  1024   // hidden
#define II  4096   // intermediate

// Scratch (device globals; allocation inside kernel_launch is forbidden)
__device__ float g_xr [E_ * CC * HH];            //  64 MB: x rounded to tf32
__device__ float g_h  [(size_t)E_ * CC * II];    // 256 MB: gelu(x@wi), tf32-rounded
__device__ float g_wiT[(size_t)E_ * II * HH];    // 128 MB: wi -> [E][I][H] (K-major)
__device__ float g_woT[(size_t)E_ * HH * II];    // 128 MB: wo -> [E][H][I] (K-major)

// ---------------------------------------------------------------- helpers

__device__ __forceinline__ uint32_t smem_u32(const void* p) {
    return (uint32_t)__cvta_generic_to_shared(p);
}

__device__ __forceinline__ float tf32r(float x) {  // round-to-nearest tf32
    uint32_t u;
    asm("cvt.rna.tf32.f32 %0, %1;" : "=r"(u) : "f"(x));
    return __uint_as_float(u);
}

__device__ __forceinline__ float gelu_exact(float v) {
    return 0.5f * v * (1.0f + erff(v * 0.70710678118654752f));
}

// ldmatrix x4: each 8x8 b16 matrix == 8x4 block of 32-bit tf32.
__device__ __forceinline__ void ldsm4(uint32_t* r, uint32_t addr) {
    asm volatile("ldmatrix.sync.aligned.m8n8.x4.shared.b16 {%0,%1,%2,%3}, [%4];"
                 : "=r"(r[0]), "=r"(r[1]), "=r"(r[2]), "=r"(r[3]) : "r"(addr));
}

// ---------------------------------------------------------------- pre-pass kernels

__global__ void round_x_kernel(const float4* __restrict__ in, float4* __restrict__ out, int n4) {
    int i = blockIdx.x * blockDim.x + threadIdx.x;
    if (i < n4) {
        float4 v = in[i];
        v.x = tf32r(v.x); v.y = tf32r(v.y); v.z = tf32r(v.z); v.w = tf32r(v.w);
        out[i] = v;
    }
}

// out[e][c][r] = tf32_round(in[e][r][c]); per-expert [R,C] -> [C,R]
__global__ void transpose_round_kernel(const float* __restrict__ in, float* __restrict__ out,
                                       int R, int C) {
    __shared__ float t[32][33];
    int e = blockIdx.z;
    const float* ip = in + (size_t)e * R * C;
    float* op = out + (size_t)e * R * C;
    int c0 = blockIdx.x * 32, r0 = blockIdx.y * 32;
    #pragma unroll
    for (int i = threadIdx.y; i < 32; i += 8)
        t[i][threadIdx.x] = ip[(size_t)(r0 + i) * C + c0 + threadIdx.x];
    __syncthreads();
    #pragma unroll
    for (int i = threadIdx.y; i < 32; i += 8)
        op[(size_t)(c0 + i) * R + r0 + threadIdx.x] = tf32r(t[threadIdx.x][i]);
}

// ---------------------------------------------------------------- tf32 mma.sync GEMM
// D[e] = A[e] (M x K, K-major) * B[e]^T (N x K, K-major); optional exact-gelu + tf32-round.
// BM=BN=128, BK=32. 256 threads = 8 warps (2 x 4); warp tile 64 x 32.
// THREE-stage cp.async pipeline, ONE __syncthreads per K-chunk.
// Fragments via ldmatrix.x4 (tf32-as-2xb16). Rows padded to 36 floats (conflict-free).

#define BK_STRIDE 36
#define TILE_F    (128 * BK_STRIDE)          // floats per tile buffer
#define STAGE_F   (2 * TILE_F)               // A tile + B tile
#define NSTAGE    3
#define SMEM_BYTES (NSTAGE * STAGE_F * 4)    // 110592 B -> still 2 CTAs/SM

__device__ __forceinline__ void mma_tf32(float* c, const uint32_t* a, const uint32_t* b) {
    asm volatile(
        "mma.sync.aligned.m16n8k8.row.col.f32.tf32.tf32.f32 "
        "{%0,%1,%2,%3}, {%4,%5,%6,%7}, {%8,%9}, {%0,%1,%2,%3};"
        : "+f"(c[0]), "+f"(c[1]), "+f"(c[2]), "+f"(c[3])
        : "r"(a[0]), "r"(a[1]), "r"(a[2]), "r"(a[3]), "r"(b[0]), "r"(b[1]));
}

__global__ __launch_bounds__(256, 2)
void gemm_tf32_kernel(const float* __restrict__ A, const float* __restrict__ B,
                      float* __restrict__ D, int M, int N, int K, int fuse_gelu) {
    extern __shared__ float smem[];

    const int tid  = threadIdx.x;
    const int wid  = tid >> 5;
    const int lane = tid & 31;
    const int wm   = wid >> 2;          // 0..1  (M direction)
    const int wn   = wid & 3;           // 0..3  (N direction)
    const int g    = lane >> 2;         // groupID 0..7
    const int tg   = lane & 3;          // thread-in-group 0..3

    const int e  = blockIdx.z;
    const int m0 = blockIdx.y * 128;
    const int n0 = blockIdx.x * 128;
    const float* Ae = A + (size_t)e * M * K + (size_t)m0 * K;
    const float* Be = B + (size_t)e * N * K + (size_t)n0 * K;
    float*       De = D + (size_t)e * M * N;

    // Loader mapping: thread t covers rows t/8 (+32,+64,+96), 16B chunk (t%8)*4 floats
    const int lr = tid >> 3;
    const int lc = (tid & 7) * 4;

    // ldmatrix per-lane source rows/col-halves (in 32-bit float units)
    const int arow  = lane & 15;
    const int acolh = (lane >> 4) << 2;
    const int brow  = ((lane & 16) >> 1) | (lane & 7);
    const int bcolh = ((lane >> 3) & 1) << 2;

    float acc[4][4][4];
    #pragma unroll
    for (int mt = 0; mt < 4; mt++)
        #pragma unroll
        for (int nt = 0; nt < 4; nt++)
            #pragma unroll
            for (int i = 0; i < 4; i++) acc[mt][nt][i] = 0.0f;

    const int KC = K >> 5;

    // One stage = A tile + B tile; per-thread cp.async source/dest helper
    auto load_stage = [&](int kc, int buf) {
        float* as = smem + buf * STAGE_F;
        float* bs = as + TILE_F;
        const float* ap = Ae + kc * 32;
        const float* bp = Be + kc * 32;
        #pragma unroll
        for (int r = 0; r < 4; r++) {
            int row = lr + r * 32;
            uint32_t da = smem_u32(as + row * BK_STRIDE + lc);
            uint32_t db = smem_u32(bs + row * BK_STRIDE + lc);
            asm volatile("cp.async.cg.shared.global [%0], [%1], 16;"
                         :: "r"(da), "l"(ap + (size_t)row * K + lc) : "memory");
            asm volatile("cp.async.cg.shared.global [%0], [%1], 16;"
                         :: "r"(db), "l"(bp + (size_t)row * K + lc) : "memory");
        }
    };

    // ---- prologue: stages 0 .. NSTAGE-2 ----
    #pragma unroll
    for (int s = 0; s < NSTAGE - 1; s++) {
        load_stage(s, s);
        asm volatile("cp.async.commit_group;" ::: "memory");
    }

    for (int kc = 0; kc < KC; kc++) {
        asm volatile("cp.async.wait_group %0;" :: "n"(NSTAGE - 2) : "memory");
        __syncthreads();   // stage kc resident everywhere; compute kc-1 finished everywhere

        // prefetch stage kc+NSTAGE-1 into the buffer freed by compute kc-1
        if (kc + NSTAGE - 1 < KC)
            load_stage(kc + NSTAGE - 1, (kc + NSTAGE - 1) % NSTAGE);
        asm volatile("cp.async.commit_group;" ::: "memory");   // may be empty; keeps counts aligned

        const float* as = smem + (kc % NSTAGE) * STAGE_F;
        const float* bs = as + TILE_F;

        uint32_t aAddr[4], bAddr[2];
        #pragma unroll
        for (int mt = 0; mt < 4; mt++)
            aAddr[mt] = smem_u32(as + (wm * 64 + mt * 16 + arow) * BK_STRIDE + acolh);
        #pragma unroll
        for (int p = 0; p < 2; p++)
            bAddr[p] = smem_u32(bs + (wn * 32 + p * 16 + brow) * BK_STRIDE + bcolh);

        #pragma unroll
        for (int ks = 0; ks < 4; ks++) {
            uint32_t af[4][4], bf[4][2];
            #pragma unroll
            for (int mt = 0; mt < 4; mt++)
                ldsm4(af[mt], aAddr[mt] + ks * 32);
            #pragma unroll
            for (int p = 0; p < 2; p++) {
                uint32_t r[4];
                ldsm4(r, bAddr[p] + ks * 32);
                bf[2 * p][0]     = r[0];  bf[2 * p][1]     = r[1];
                bf[2 * p + 1][0] = r[2];  bf[2 * p + 1][1] = r[3];
            }
            #pragma unroll
            for (int mt = 0; mt < 4; mt++)
                #pragma unroll
                for (int nt = 0; nt < 4; nt++)
                    mma_tf32(acc[mt][nt], af[mt], bf[nt]);
        }
    }

    // ---- epilogue ----
    #pragma unroll
    for (int mt = 0; mt < 4; mt++) {
        #pragma unroll
        for (int nt = 0; nt < 4; nt++) {
            int row = m0 + wm * 64 + mt * 16 + g;
            int col = n0 + wn * 32 + nt * 8 + tg * 2;
            float v0 = acc[mt][nt][0], v1 = acc[mt][nt][1];
            float v2 = acc[mt][nt][2], v3 = acc[mt][nt][3];
            if (fuse_gelu) {
                v0 = tf32r(gelu_exact(v0));
                v1 = tf32r(gelu_exact(v1));
                v2 = tf32r(gelu_exact(v2));
                v3 = tf32r(gelu_exact(v3));
            }
            *(float2*)(De + (size_t)row * N + col)       = make_float2(v0, v1);
            *(float2*)(De + (size_t)(row + 8) * N + col) = make_float2(v2, v3);
        }
    }
}

// ---------------------------------------------------------------- launch

extern "C" void kernel_launch(void* const* d_in, const int* in_sizes, int n_in,
                              void* d_out, int out_size) {
    const float* x  = (const float*)d_in[0];  // [1, 8, 2048, 1024]
    const float* wi = (const float*)d_in[1];  // [8, 1024, 4096]
    const float* wo = (const float*)d_in[2];  // [8, 4096, 1024]
    float* out = (float*)d_out;               // [1, 8, 2048, 1024]

    float *xr = nullptr, *h = nullptr, *wiT = nullptr, *woT = nullptr;
    cudaGetSymbolAddress((void**)&xr,  g_xr);
    cudaGetSymbolAddress((void**)&h,   g_h);
    cudaGetSymbolAddress((void**)&wiT, g_wiT);
    cudaGetSymbolAddress((void**)&woT, g_woT);

    cudaFuncSetAttribute(gemm_tf32_kernel,
                         cudaFuncAttributeMaxDynamicSharedMemorySize, SMEM_BYTES);

    // 1) round x to tf32 (RNE) so the MMA's truncation is lossless
    int n4 = (E_ * CC * HH) / 4;
    round_x_kernel<<<(n4 + 255) / 256, 256>>>((const float4*)x, (float4*)xr, n4);

    // 2) transpose weights to K-major (+ tf32 RNE rounding)
    transpose_round_kernel<<<dim3(II / 32, HH / 32, E_), dim3(32, 8)>>>(wi, wiT, HH, II);
    transpose_round_kernel<<<dim3(HH / 32, II / 32, E_), dim3(32, 8)>>>(wo, woT, II, HH);

    // 3) GEMM1 + gelu: h[e] = gelu(x[e] @ wi[e])   (M=2048, N=4096, K=1024)
    gemm_tf32_kernel<<<dim3(II / 128, CC / 128, E_), 256, SMEM_BYTES>>>(xr, wiT, h, CC, II, HH, 1);

    // 4) GEMM2: out[e] = h[e] @ wo[e]              (M=2048, N=1024, K=4096)
    gemm_tf32_kernel<<<dim3(HH / 128, CC / 128, E_), 256, SMEM_BYTES>>>(h, woT, out, CC, HH, II, 0);
}

// round 12
// speedup vs baseline: 1.2420x; 1.2420x over previous
#include <cuda_runtime.h>
#include <cuda_bf16.h>
#include <cstdint>
#include <math.h>

// Problem constants
#define E_  8
#define CC  2048   // tokens per expert (G*C)
#define HH  1024   // hidden
#define II  4096   // intermediate

// Scratch (device globals; allocation inside kernel_launch is forbidden)
__device__ float g_xr [E_ * CC * HH];            //  64 MB: x rounded to tf32
__device__ float g_h  [(size_t)E_ * CC * II];    // 256 MB: gelu(x@wi), tf32-rounded
__device__ float g_wiT[(size_t)E_ * II * HH];    // 128 MB: wi -> [E][I][H] (K-major)
__device__ float g_woT[(size_t)E_ * HH * II];    // 128 MB: wo -> [E][H][I] (K-major)

// ---------------------------------------------------------------- helpers

__device__ __forceinline__ uint32_t smem_u32(const void* p) {
    return (uint32_t)__cvta_generic_to_shared(p);
}

__device__ __forceinline__ float tf32r(float x) {  // round-to-nearest tf32
    uint32_t u;
    asm("cvt.rna.tf32.f32 %0, %1;" : "=r"(u) : "f"(x));
    return __uint_as_float(u);
}

__device__ __forceinline__ float gelu_exact(float v) {
    return 0.5f * v * (1.0f + erff(v * 0.70710678118654752f));
}

// ldmatrix x4: each 8x8 b16 matrix == 8x4 block of 32-bit tf32.
__device__ __forceinline__ void ldsm4(uint32_t* r, uint32_t addr) {
    asm volatile("ldmatrix.sync.aligned.m8n8.x4.shared.b16 {%0,%1,%2,%3}, [%4];"
                 : "=r"(r[0]), "=r"(r[1]), "=r"(r[2]), "=r"(r[3]) : "r"(addr));
}

// ---------------------------------------------------------------- pre-pass kernels

__global__ void round_x_kernel(const float4* __restrict__ in, float4* __restrict__ out, int n4) {
    int i = blockIdx.x * blockDim.x + threadIdx.x;
    if (i < n4) {
        float4 v = in[i];
        v.x = tf32r(v.x); v.y = tf32r(v.y); v.z = tf32r(v.z); v.w = tf32r(v.w);
        out[i] = v;
    }
}

// out[e][c][r] = tf32_round(in[e][r][c]); per-expert [R,C] -> [C,R]
__global__ void transpose_round_kernel(const float* __restrict__ in, float* __restrict__ out,
                                       int R, int C) {
    __shared__ float t[32][33];
    int e = blockIdx.z;
    const float* ip = in + (size_t)e * R * C;
    float* op = out + (size_t)e * R * C;
    int c0 = blockIdx.x * 32, r0 = blockIdx.y * 32;
    #pragma unroll
    for (int i = threadIdx.y; i < 32; i += 8)
        t[i][threadIdx.x] = ip[(size_t)(r0 + i) * C + c0 + threadIdx.x];
    __syncthreads();
    #pragma unroll
    for (int i = threadIdx.y; i < 32; i += 8)
        op[(size_t)(c0 + i) * R + r0 + threadIdx.x] = tf32r(t[threadIdx.x][i]);
}

// ---------------------------------------------------------------- tf32 mma.sync GEMM
// D[e] = A[e] (M x K, K-major) * B[e]^T (N x K, K-major); optional exact-gelu + tf32-round.
// BM=128, BN=256, BK=32. 256 threads = 8 warps (2 x 4); warp tile 64 x 64.
// FOUR-stage cp.async pipeline, R4-proven ordering per chunk:
//   prefetch(kc+3) -> commit -> wait_group 2 -> sync -> compute(kc) -> sync
// (sync AFTER wait is required for cross-thread cp.async visibility — R6 lesson.)
// One CTA/SM (221KB smem); latency hidden by pipeline depth, regs free to 255.
// Fragments via ldmatrix.x4 (tf32-as-2xb16). Rows padded to 36 floats (conflict-free).

#define BKS       36                         // smem row stride in floats
#define TILE_A_F  (128 * BKS)
#define TILE_B_F  (256 * BKS)
#define STAGE_F   (TILE_A_F + TILE_B_F)      // 13824 floats
#define STAGE_BYTES (STAGE_F * 4)            // 55296 B
#define NSTAGE    4
#define SMEM_BYTES (NSTAGE * STAGE_BYTES)    // 221184 B -> 1 CTA/SM

__device__ __forceinline__ void mma_tf32(float* c, const uint32_t* a, const uint32_t* b) {
    asm volatile(
        "mma.sync.aligned.m16n8k8.row.col.f32.tf32.tf32.f32 "
        "{%0,%1,%2,%3}, {%4,%5,%6,%7}, {%8,%9}, {%0,%1,%2,%3};"
        : "+f"(c[0]), "+f"(c[1]), "+f"(c[2]), "+f"(c[3])
        : "r"(a[0]), "r"(a[1]), "r"(a[2]), "r"(a[3]), "r"(b[0]), "r"(b[1]));
}

__global__ __launch_bounds__(256, 1)
void gemm_tf32_kernel(const float* __restrict__ A, const float* __restrict__ B,
                      float* __restrict__ D, int M, int N, int K, int fuse_gelu) {
    extern __shared__ float smem[];

    const int tid  = threadIdx.x;
    const int wid  = tid >> 5;
    const int lane = tid & 31;
    const int wm   = wid >> 2;          // 0..1  (M direction, 64 rows each)
    const int wn   = wid & 3;           // 0..3  (N direction, 64 cols each)
    const int g    = lane >> 2;         // groupID 0..7
    const int tg   = lane & 3;          // thread-in-group 0..3

    const int e  = blockIdx.z;
    const int m0 = blockIdx.y * 128;
    const int n0 = blockIdx.x * 256;
    const float* Ae = A + (size_t)e * M * K + (size_t)m0 * K;
    const float* Be = B + (size_t)e * N * K + (size_t)n0 * K;
    float*       De = D + (size_t)e * M * N;

    // Loader mapping: thread t covers rows lr (+32 strides), 16B chunk (t%8)*4 floats
    const int lr = tid >> 3;            // 0..31
    const int lc = (tid & 7) * 4;

    // ldmatrix per-lane source rows/col-halves (in 32-bit float units)
    const int arow  = lane & 15;
    const int acolh = (lane >> 4) << 2;
    const int brow  = ((lane & 16) >> 1) | (lane & 7);
    const int bcolh = ((lane >> 3) & 1) << 2;

    // Fragment base addresses for buffer 0 (buffer b = +b*STAGE_BYTES)
    uint32_t aAddr0[4], bAddr0[4];
    #pragma unroll
    for (int mt = 0; mt < 4; mt++)
        aAddr0[mt] = smem_u32(smem + (wm * 64 + mt * 16 + arow) * BKS + acolh);
    #pragma unroll
    for (int p = 0; p < 4; p++)
        bAddr0[p] = smem_u32(smem + TILE_A_F + (wn * 64 + p * 16 + brow) * BKS + bcolh);

    float acc[4][8][4];
    #pragma unroll
    for (int mt = 0; mt < 4; mt++)
        #pragma unroll
        for (int nt = 0; nt < 8; nt++)
            #pragma unroll
            for (int i = 0; i < 4; i++) acc[mt][nt][i] = 0.0f;

    const int KC = K >> 5;

    auto load_stage = [&](int kc, int buf) {
        float* as = smem + buf * STAGE_F;
        float* bs = as + TILE_A_F;
        const float* ap = Ae + kc * 32;
        const float* bp = Be + kc * 32;
        #pragma unroll
        for (int r = 0; r < 4; r++) {       // A: 128 rows
            int row = lr + r * 32;
            uint32_t da = smem_u32(as + row * BKS + lc);
            asm volatile("cp.async.cg.shared.global [%0], [%1], 16;"
                         :: "r"(da), "l"(ap + (size_t)row * K + lc) : "memory");
        }
        #pragma unroll
        for (int r = 0; r < 8; r++) {       // B: 256 rows
            int row = lr + r * 32;
            uint32_t db = smem_u32(bs + row * BKS + lc);
            asm volatile("cp.async.cg.shared.global [%0], [%1], 16;"
                         :: "r"(db), "l"(bp + (size_t)row * K + lc) : "memory");
        }
    };

    // ---- prologue: stages 0..NSTAGE-2 ----
    #pragma unroll
    for (int s = 0; s < NSTAGE - 1; s++) {
        load_stage(s, s);
        asm volatile("cp.async.commit_group;" ::: "memory");
    }

    for (int kc = 0; kc < KC; kc++) {
        // prefetch before wait (trailing sync of prev iter guarantees the buffer is free)
        if (kc + NSTAGE - 1 < KC)
            load_stage(kc + NSTAGE - 1, (kc + NSTAGE - 1) % NSTAGE);
        asm volatile("cp.async.commit_group;" ::: "memory");   // empty at tail keeps counts aligned

        asm volatile("cp.async.wait_group %0;" :: "n"(NSTAGE - 2) : "memory");
        __syncthreads();   // cross-thread visibility of stage kc (mandatory after wait)

        const uint32_t boff = (uint32_t)(kc % NSTAGE) * STAGE_BYTES;

        #pragma unroll
        for (int ks = 0; ks < 4; ks++) {
            uint32_t af[4][4], bf[8][2];
            #pragma unroll
            for (int mt = 0; mt < 4; mt++)
                ldsm4(af[mt], aAddr0[mt] + boff + ks * 32);
            #pragma unroll
            for (int p = 0; p < 4; p++) {
                uint32_t r[4];
                ldsm4(r, bAddr0[p] + boff + ks * 32);
                bf[2 * p][0]     = r[0];  bf[2 * p][1]     = r[1];
                bf[2 * p + 1][0] = r[2];  bf[2 * p + 1][1] = r[3];
            }
            #pragma unroll
            for (int mt = 0; mt < 4; mt++)
                #pragma unroll
                for (int nt = 0; nt < 8; nt++)
                    mma_tf32(acc[mt][nt], af[mt], bf[nt]);
        }
        __syncthreads();   // all warps done with buffer before next prefetch overwrites
    }

    // ---- epilogue ----
    #pragma unroll
    for (int mt = 0; mt < 4; mt++) {
        #pragma unroll
        for (int nt = 0; nt < 8; nt++) {
            int row = m0 + wm * 64 + mt * 16 + g;
            int col = n0 + wn * 64 + nt * 8 + tg * 2;
            float v0 = acc[mt][nt][0], v1 = acc[mt][nt][1];
            float v2 = acc[mt][nt][2], v3 = acc[mt][nt][3];
            if (fuse_gelu) {
                v0 = tf32r(gelu_exact(v0));
                v1 = tf32r(gelu_exact(v1));
                v2 = tf32r(gelu_exact(v2));
                v3 = tf32r(gelu_exact(v3));
            }
            *(float2*)(De + (size_t)row * N + col)       = make_float2(v0, v1);
            *(float2*)(De + (size_t)(row + 8) * N + col) = make_float2(v2, v3);
        }
    }
}

// ---------------------------------------------------------------- launch

extern "C" void kernel_launch(void* const* d_in, const int* in_sizes, int n_in,
                              void* d_out, int out_size) {
    const float* x  = (const float*)d_in[0];  // [1, 8, 2048, 1024]
    const float* wi = (const float*)d_in[1];  // [8, 1024, 4096]
    const float* wo = (const float*)d_in[2];  // [8, 4096, 1024]
    float* out = (float*)d_out;               // [1, 8, 2048, 1024]

    float *xr = nullptr, *h = nullptr, *wiT = nullptr, *woT = nullptr;
    cudaGetSymbolAddress((void**)&xr,  g_xr);
    cudaGetSymbolAddress((void**)&h,   g_h);
    cudaGetSymbolAddress((void**)&wiT, g_wiT);
    cudaGetSymbolAddress((void**)&woT, g_woT);

    cudaFuncSetAttribute(gemm_tf32_kernel,
                         cudaFuncAttributeMaxDynamicSharedMemorySize, SMEM_BYTES);

    // 1) round x to tf32 (RNE) so the MMA's truncation is lossless
    int n4 = (E_ * CC * HH) / 4;
    round_x_kernel<<<(n4 + 255) / 256, 256>>>((const float4*)x, (float4*)xr, n4);

    // 2) transpose weights to K-major (+ tf32 RNE rounding)
    transpose_round_kernel<<<dim3(II / 32, HH / 32, E_), dim3(32, 8)>>>(wi, wiT, HH, II);
    transpose_round_kernel<<<dim3(HH / 32, II / 32, E_), dim3(32, 8)>>>(wo, woT, II, HH);

    // 3) GEMM1 + gelu: h[e] = gelu(x[e] @ wi[e])   (M=2048, N=4096, K=1024)
    gemm_tf32_kernel<<<dim3(II / 256, CC / 128, E_), 256, SMEM_BYTES>>>(xr, wiT, h, CC, II, HH, 1);

    // 4) GEMM2: out[e] = h[e] @ wo[e]              (M=2048, N=1024, K=4096)
    gemm_tf32_kernel<<<dim3(HH / 256, CC / 128, E_), 256, SMEM_BYTES>>>(h, woT, out, CC, HH, II, 0);
}

// round 13
// speedup vs baseline: 1.5098x; 1.2156x over previous
#include <cuda_runtime.h>
#include <cuda_bf16.h>
#include <cstdint>
#include <math.h>

// Problem constants
#define E_  8
#define CC  2048   // tokens per expert (G*C)
#define HH  1024   // hidden
#define II  4096   // intermediate

// Scratch (device globals; allocation inside kernel_launch is forbidden)
__device__ float g_xr [E_ * CC * HH];            //  64 MB: x rounded to tf32
__device__ float g_h  [(size_t)E_ * CC * II];    // 256 MB: gelu(x@wi), tf32-rounded
__device__ float g_wiT[(size_t)E_ * II * HH];    // 128 MB: wi -> [E][I][H] (K-major)
__device__ float g_woT[(size_t)E_ * HH * II];    // 128 MB: wo -> [E][H][I] (K-major)

// ---------------------------------------------------------------- helpers

__device__ __forceinline__ uint32_t smem_u32(const void* p) {
    return (uint32_t)__cvta_generic_to_shared(p);
}

__device__ __forceinline__ float tf32r(float x) {  // round-to-nearest tf32
    uint32_t u;
    asm("cvt.rna.tf32.f32 %0, %1;" : "=r"(u) : "f"(x));
    return __uint_as_float(u);
}

__device__ __forceinline__ float gelu_exact(float v) {
    return 0.5f * v * (1.0f + erff(v * 0.70710678118654752f));
}

// ldmatrix x4: each 8x8 b16 matrix == 8x4 block of 32-bit tf32.
__device__ __forceinline__ void ldsm4(uint32_t* r, uint32_t addr) {
    asm volatile("ldmatrix.sync.aligned.m8n8.x4.shared.b16 {%0,%1,%2,%3}, [%4];"
                 : "=r"(r[0]), "=r"(r[1]), "=r"(r[2]), "=r"(r[3]) : "r"(addr));
}

// ---------------------------------------------------------------- pre-pass kernels

__global__ void round_x_kernel(const float4* __restrict__ in, float4* __restrict__ out, int n4) {
    int i = blockIdx.x * blockDim.x + threadIdx.x;
    if (i < n4) {
        float4 v = in[i];
        v.x = tf32r(v.x); v.y = tf32r(v.y); v.z = tf32r(v.z); v.w = tf32r(v.w);
        out[i] = v;
    }
}

// out[e][c][r] = tf32_round(in[e][r][c]); per-expert [R,C] -> [C,R]
__global__ void transpose_round_kernel(const float* __restrict__ in, float* __restrict__ out,
                                       int R, int C) {
    __shared__ float t[32][33];
    int e = blockIdx.z;
    const float* ip = in + (size_t)e * R * C;
    float* op = out + (size_t)e * R * C;
    int c0 = blockIdx.x * 32, r0 = blockIdx.y * 32;
    #pragma unroll
    for (int i = threadIdx.y; i < 32; i += 8)
        t[i][threadIdx.x] = ip[(size_t)(r0 + i) * C + c0 + threadIdx.x];
    __syncthreads();
    #pragma unroll
    for (int i = threadIdx.y; i < 32; i += 8)
        op[(size_t)(c0 + i) * R + r0 + threadIdx.x] = tf32r(t[threadIdx.x][i]);
}

// ---------------------------------------------------------------- tf32 mma.sync GEMM
// D[e] = A[e] (M x K, K-major) * B[e]^T (N x K, K-major); optional exact-gelu + tf32-round.
// BM=BN=128, BK=32. 256 threads = 8 warps (2 x 4); warp tile 64 x 32. 2 CTAs/SM.
// THREE-stage cp.async pipeline with the R4-proven per-chunk ordering:
//   prefetch(kc+2) -> commit -> wait_group 2 -> sync -> compute(kc) -> sync
// Stage kc was issued 2 chunks ago, so the wait is (nearly) free; sync-after-wait
// gives cross-thread cp.async visibility (R6 lesson); trailing sync frees buffers.
// Fragments via ldmatrix.x4 (tf32-as-2xb16). Rows padded to 36 floats (conflict-free).

#define BK_STRIDE 36
#define TILE_F    (128 * BK_STRIDE)          // floats per tile buffer
#define STAGE_F   (2 * TILE_F)               // A tile + B tile
#define STAGE_BYTES (STAGE_F * 4)            // 36864 B
#define NSTAGE    3
#define SMEM_BYTES (NSTAGE * STAGE_BYTES)    // 110592 B -> 2 CTAs/SM (216KB)

__device__ __forceinline__ void mma_tf32(float* c, const uint32_t* a, const uint32_t* b) {
    asm volatile(
        "mma.sync.aligned.m16n8k8.row.col.f32.tf32.tf32.f32 "
        "{%0,%1,%2,%3}, {%4,%5,%6,%7}, {%8,%9}, {%0,%1,%2,%3};"
        : "+f"(c[0]), "+f"(c[1]), "+f"(c[2]), "+f"(c[3])
        : "r"(a[0]), "r"(a[1]), "r"(a[2]), "r"(a[3]), "r"(b[0]), "r"(b[1]));
}

__global__ __launch_bounds__(256, 2)
void gemm_tf32_kernel(const float* __restrict__ A, const float* __restrict__ B,
                      float* __restrict__ D, int M, int N, int K, int fuse_gelu) {
    extern __shared__ float smem[];

    const int tid  = threadIdx.x;
    const int wid  = tid >> 5;
    const int lane = tid & 31;
    const int wm   = wid >> 2;          // 0..1  (M direction)
    const int wn   = wid & 3;           // 0..3  (N direction)
    const int g    = lane >> 2;         // groupID 0..7
    const int tg   = lane & 3;          // thread-in-group 0..3

    const int e  = blockIdx.z;
    const int m0 = blockIdx.y * 128;
    const int n0 = blockIdx.x * 128;
    const float* Ae = A + (size_t)e * M * K + (size_t)m0 * K;
    const float* Be = B + (size_t)e * N * K + (size_t)n0 * K;
    float*       De = D + (size_t)e * M * N;

    // Loader mapping: thread t covers rows t/8 (+32,+64,+96), 16B chunk (t%8)*4 floats
    const int lr = tid >> 3;
    const int lc = (tid & 7) * 4;

    // ldmatrix per-lane source rows/col-halves (in 32-bit float units)
    const int arow  = lane & 15;
    const int acolh = (lane >> 4) << 2;
    const int brow  = ((lane & 16) >> 1) | (lane & 7);
    const int bcolh = ((lane >> 3) & 1) << 2;

    // Fragment base addresses for buffer 0 (buffer b = +b*STAGE_BYTES)
    uint32_t aAddr0[4], bAddr0[2];
    #pragma unroll
    for (int mt = 0; mt < 4; mt++)
        aAddr0[mt] = smem_u32(smem + (wm * 64 + mt * 16 + arow) * BK_STRIDE + acolh);
    #pragma unroll
    for (int p = 0; p < 2; p++)
        bAddr0[p] = smem_u32(smem + TILE_F + (wn * 32 + p * 16 + brow) * BK_STRIDE + bcolh);

    float acc[4][4][4];
    #pragma unroll
    for (int mt = 0; mt < 4; mt++)
        #pragma unroll
        for (int nt = 0; nt < 4; nt++)
            #pragma unroll
            for (int i = 0; i < 4; i++) acc[mt][nt][i] = 0.0f;

    const int KC = K >> 5;

    auto load_stage = [&](int kc, int buf) {
        float* as = smem + buf * STAGE_F;
        float* bs = as + TILE_F;
        const float* ap = Ae + kc * 32;
        const float* bp = Be + kc * 32;
        #pragma unroll
        for (int r = 0; r < 4; r++) {
            int row = lr + r * 32;
            uint32_t da = smem_u32(as + row * BK_STRIDE + lc);
            uint32_t db = smem_u32(bs + row * BK_STRIDE + lc);
            asm volatile("cp.async.cg.shared.global [%0], [%1], 16;"
                         :: "r"(da), "l"(ap + (size_t)row * K + lc) : "memory");
            asm volatile("cp.async.cg.shared.global [%0], [%1], 16;"
                         :: "r"(db), "l"(bp + (size_t)row * K + lc) : "memory");
        }
    };

    // ---- prologue: stages 0..NSTAGE-2 ----
    #pragma unroll
    for (int s = 0; s < NSTAGE - 1; s++) {
        load_stage(s, s);
        asm volatile("cp.async.commit_group;" ::: "memory");
    }

    for (int kc = 0; kc < KC; kc++) {
        // prefetch before wait: trailing sync of prev iter guarantees buf (kc+2)%3 is free
        if (kc + NSTAGE - 1 < KC)
            load_stage(kc + NSTAGE - 1, (kc + NSTAGE - 1) % NSTAGE);
        asm volatile("cp.async.commit_group;" ::: "memory");   // empty at tail keeps counts aligned

        // allow NSTAGE-1 pending groups -> stage kc complete (issued 2 chunks ago)
        asm volatile("cp.async.wait_group %0;" :: "n"(NSTAGE - 1) : "memory");
        __syncthreads();   // cross-thread visibility of stage kc (mandatory after wait)

        const uint32_t boff = (uint32_t)(kc % NSTAGE) * STAGE_BYTES;

        #pragma unroll
        for (int ks = 0; ks < 4; ks++) {
            uint32_t af[4][4], bf[4][2];
            #pragma unroll
            for (int mt = 0; mt < 4; mt++)
                ldsm4(af[mt], aAddr0[mt] + boff + ks * 32);
            #pragma unroll
            for (int p = 0; p < 2; p++) {
                uint32_t r[4];
                ldsm4(r, bAddr0[p] + boff + ks * 32);
                bf[2 * p][0]     = r[0];  bf[2 * p][1]     = r[1];
                bf[2 * p + 1][0] = r[2];  bf[2 * p + 1][1] = r[3];
            }
            #pragma unroll
            for (int mt = 0; mt < 4; mt++)
                #pragma unroll
                for (int nt = 0; nt < 4; nt++)
                    mma_tf32(acc[mt][nt], af[mt], bf[nt]);
        }
        __syncthreads();   // all warps done with buffer before a later prefetch overwrites
    }

    // ---- epilogue ----
    #pragma unroll
    for (int mt = 0; mt < 4; mt++) {
        #pragma unroll
        for (int nt = 0; nt < 4; nt++) {
            int row = m0 + wm * 64 + mt * 16 + g;
            int col = n0 + wn * 32 + nt * 8 + tg * 2;
            float v0 = acc[mt][nt][0], v1 = acc[mt][nt][1];
            float v2 = acc[mt][nt][2], v3 = acc[mt][nt][3];
            if (fuse_gelu) {
                v0 = tf32r(gelu_exact(v0));
                v1 = tf32r(gelu_exact(v1));
                v2 = tf32r(gelu_exact(v2));
                v3 = tf32r(gelu_exact(v3));
            }
            *(float2*)(De + (size_t)row * N + col)       = make_float2(v0, v1);
            *(float2*)(De + (size_t)(row + 8) * N + col) = make_float2(v2, v3);
        }
    }
}

// ---------------------------------------------------------------- launch

extern "C" void kernel_launch(void* const* d_in, const int* in_sizes, int n_in,
                              void* d_out, int out_size) {
    const float* x  = (const float*)d_in[0];  // [1, 8, 2048, 1024]
    const float* wi = (const float*)d_in[1];  // [8, 1024, 4096]
    const float* wo = (const float*)d_in[2];  // [8, 4096, 1024]
    float* out = (float*)d_out;               // [1, 8, 2048, 1024]

    float *xr = nullptr, *h = nullptr, *wiT = nullptr, *woT = nullptr;
    cudaGetSymbolAddress((void**)&xr,  g_xr);
    cudaGetSymbolAddress((void**)&h,   g_h);
    cudaGetSymbolAddress((void**)&wiT, g_wiT);
    cudaGetSymbolAddress((void**)&woT, g_woT);

    cudaFuncSetAttribute(gemm_tf32_kernel,
                         cudaFuncAttributeMaxDynamicSharedMemorySize, SMEM_BYTES);

    // 1) round x to tf32 (RNE) so the MMA's truncation is lossless
    int n4 = (E_ * CC * HH) / 4;
    round_x_kernel<<<(n4 + 255) / 256, 256>>>((const float4*)x, (float4*)xr, n4);

    // 2) transpose weights to K-major (+ tf32 RNE rounding)
    transpose_round_kernel<<<dim3(II / 32, HH / 32, E_), dim3(32, 8)>>>(wi, wiT, HH, II);
    transpose_round_kernel<<<dim3(HH / 32, II / 32, E_), dim3(32, 8)>>>(wo, woT, II, HH);

    // 3) GEMM1 + gelu: h[e] = gelu(x[e] @ wi[e])   (M=2048, N=4096, K=1024)
    gemm_tf32_kernel<<<dim3(II / 128, CC / 128, E_), 256, SMEM_BYTES>>>(xr, wiT, h, CC, II, HH, 1);

    // 4) GEMM2: out[e] = h[e] @ wo[e]              (M=2048, N=1024, K=4096)
    gemm_tf32_kernel<<<dim3(HH / 128, CC / 128, E_), 256, SMEM_BYTES>>>(h, woT, out, CC, HH, II, 0);
}